// round 2
// baseline (speedup 1.0000x reference)
#include <cuda_runtime.h>
#include <cstdio>

#define BB 4
#define NSS 96
#define TT 8
#define HD 256
#define H4 1024
#define NN 97
#define NLAY 6
#define ROWS (BB*NN)     // 388
#define SEQS (BB*NSS)    // 384
#define TOK  (SEQS*TT)   // 3072

// ---------------- scratch (static device memory; no runtime allocs) -------
__device__ float g_xw[TOK*H4];        // token @ Wx_s + b_s
__device__ float g_z[SEQS*H4];        // per-step LSTM preactivations
__device__ float g_c0[SEQS*HD];
__device__ float g_h0[SEQS*HD];       // statement embeddings after T steps
__device__ float g_pref[ROWS*HD];     // prefix sums, [B,97,H]
__device__ float g_Me[HD*H4];         // W_se @ Wx_e
__device__ float g_Ms[HD*HD];         // W_se @ W_sd
__device__ float g_be[H4];            // b_se@Wx_e + b_e
__device__ float g_bs[HD];            // b_se@W_sd + b_sd
__device__ float g_pm4[ROWS*H4];      // pref @ Me
__device__ float g_prefS[ROWS*HD];    // pref @ Ms
__device__ float g_S2[BB*NN*NN];      // layer-invariant logit part
__device__ float g_aArr[ROWS];        // per-layer logit part (row term)
__device__ float g_hWhb[ROWS*H4];     // h @ Wh_e + be
__device__ float g_w[BB*NN*NN];       // skip_p * p[i]
__device__ float g_cA[ROWS*HD], g_hA[ROWS*HD];
__device__ float g_cB[ROWS*HD], g_hB[ROWS*HD];
__device__ float g_pA[ROWS], g_pB[ROWS];

__device__ __forceinline__ float sigf(float x)  { return 1.0f / (1.0f + __expf(-x)); }
__device__ __forceinline__ float tanhr(float x) { return 2.0f / (1.0f + __expf(-2.0f * x)) - 1.0f; }

// ---------------- generic fp32 tiled GEMM: C = opt(gather)A @ B (+bias)(+addM)
#define BM 64
#define BN 64
#define BK 16
__global__ void gemm_kernel(const float* __restrict__ A, const int* __restrict__ gidx,
                            const float* __restrict__ B, const float* __restrict__ bias,
                            const float* __restrict__ addM, int addStride,
                            float* __restrict__ C, int M, int K, int N) {
    __shared__ float sA[BK][BM];
    __shared__ float sB[BK][BN];
    int bm = blockIdx.x * BM;
    int bn = blockIdx.y * BN;
    int tid = threadIdx.x;
    int tr = (tid >> 4) << 2;
    int tc = (tid & 15) << 2;
    float acc[4][4] = {};
    for (int k0 = 0; k0 < K; k0 += BK) {
#pragma unroll
        for (int l = 0; l < 4; l++) {
            int idx = tid + l * 256;
            int r = idx / BK, kk = idx % BK;
            int grow = bm + r;
            float v = 0.f;
            if (grow < M) {
                int arow = gidx ? gidx[grow] : grow;
                v = A[(size_t)arow * K + k0 + kk];
            }
            sA[kk][r] = v;
        }
#pragma unroll
        for (int l = 0; l < 4; l++) {
            int idx = tid + l * 256;
            int kk = idx / BN, c = idx % BN;
            sB[kk][c] = B[(size_t)(k0 + kk) * N + bn + c];
        }
        __syncthreads();
#pragma unroll
        for (int kk = 0; kk < BK; kk++) {
            float a0 = sA[kk][tr], a1 = sA[kk][tr + 1], a2 = sA[kk][tr + 2], a3 = sA[kk][tr + 3];
            float b0 = sB[kk][tc], b1 = sB[kk][tc + 1], b2 = sB[kk][tc + 2], b3 = sB[kk][tc + 3];
            acc[0][0] += a0 * b0; acc[0][1] += a0 * b1; acc[0][2] += a0 * b2; acc[0][3] += a0 * b3;
            acc[1][0] += a1 * b0; acc[1][1] += a1 * b1; acc[1][2] += a1 * b2; acc[1][3] += a1 * b3;
            acc[2][0] += a2 * b0; acc[2][1] += a2 * b1; acc[2][2] += a2 * b2; acc[2][3] += a2 * b3;
            acc[3][0] += a3 * b0; acc[3][1] += a3 * b1; acc[3][2] += a3 * b2; acc[3][3] += a3 * b3;
        }
        __syncthreads();
    }
#pragma unroll
    for (int r = 0; r < 4; r++) {
        int grow = bm + tr + r;
        if (grow >= M) continue;
#pragma unroll
        for (int c = 0; c < 4; c++) {
            int gcol = bn + tc + c;
            float v = acc[r][c];
            if (bias) v += bias[gcol];
            if (addM) v += addM[(size_t)grow * addStride + gcol];
            C[(size_t)grow * N + gcol] = v;
        }
    }
}

// ---------------- statement LSTM gate update --------------------------------
__global__ void lstm_gate_kernel(const float* __restrict__ z, int zstride,
                                 float* __restrict__ c, float* __restrict__ h, int first) {
    int idx = blockIdx.x * blockDim.x + threadIdx.x;
    if (idx >= SEQS * HD) return;
    int s = idx / HD, hh = idx % HD;
    const float* zr = z + (size_t)s * zstride;
    float zi = zr[hh], zf = zr[HD + hh], zg = zr[2 * HD + hh], zo = zr[3 * HD + hh];
    float cp = first ? 0.f : c[idx];
    float c2 = sigf(zf) * cp + sigf(zi) * tanhr(zg);
    h[idx] = sigf(zo) * tanhr(c2);
    c[idx] = c2;
}

// ---------------- prefix sums over statements -------------------------------
__global__ void cumsum_kernel(const float* __restrict__ stmt, float* __restrict__ pref) {
    int b = blockIdx.x, hh = threadIdx.x;
    float acc = 0.f;
    pref[(size_t)(b * NN) * HD + hh] = 0.f;
    for (int k = 1; k < NN; k++) {
        acc += stmt[(size_t)(b * NSS + k - 1) * HD + hh];
        pref[(size_t)(b * NN + k) * HD + hh] = acc;
    }
}

// ---------------- vec @ mat (+bias) -----------------------------------------
__global__ void vecmat_kernel(const float* __restrict__ v, const float* __restrict__ Bm,
                              const float* __restrict__ bias, float* __restrict__ out,
                              int K, int N) {
    int n = blockIdx.x * blockDim.x + threadIdx.x;
    if (n >= N) return;
    float acc = bias ? bias[n] : 0.f;
    for (int k = 0; k < K; k++) acc += v[k] * Bm[(size_t)k * N + n];
    out[n] = acc;
}

// ---------------- layer-invariant logit term S2 -----------------------------
__global__ void s2_kernel(const float* __restrict__ prefS, const float* __restrict__ bs,
                          const float* __restrict__ W_d1, float* __restrict__ S2) {
    int bi = blockIdx.x;               // b*97 + i
    int b = bi / NN;
    int lane = threadIdx.x & 31, warp = threadIdx.x >> 5;
    const float* pi = prefS + (size_t)bi * HD;
    for (int j = warp; j < NN; j += 4) {
        const float* pj = prefS + (size_t)(b * NN + j) * HD;
        float acc = 0.f;
#pragma unroll
        for (int l = 0; l < 8; l++) {
            int hh = lane + l * 32;
            float v = pj[hh] - pi[hh] + bs[hh];
            acc += fmaxf(v, 0.f) * W_d1[HD + hh];
        }
        for (int o = 16; o; o >>= 1) acc += __shfl_xor_sync(0xFFFFFFFFu, acc, o);
        if (lane == 0) S2[(size_t)bi * NN + j] = acc;
    }
}

// ---------------- exec state init -------------------------------------------
__global__ void init_exec_kernel(const float* __restrict__ ia, const float* __restrict__ ib,
                                 float* __restrict__ c, float* __restrict__ h,
                                 float* __restrict__ p) {
    int idx = blockIdx.x * blockDim.x + threadIdx.x;
    if (idx < ROWS * HD) { c[idx] = ia[idx % HD]; h[idx] = ib[idx % HD]; }
    if (idx < ROWS) p[idx] = (idx % NN == 0) ? 1.f : 0.f;
}

// ---------------- per-layer: h_key row term ---------------------------------
__global__ void hkey_kernel(const float* __restrict__ h, const float* __restrict__ W_hk,
                            const float* __restrict__ b_hk, const float* __restrict__ W_d1,
                            float* __restrict__ aOut) {
    int row = blockIdx.x, hh = threadIdx.x;
    __shared__ float sh[HD];
    __shared__ float red[HD];
    sh[hh] = h[(size_t)row * HD + hh];
    __syncthreads();
    float acc = b_hk[hh];
    for (int k = 0; k < HD; k++) acc += sh[k] * W_hk[(size_t)k * HD + hh];
    red[hh] = fmaxf(acc, 0.f) * W_d1[hh];
    __syncthreads();
    for (int s = 128; s > 0; s >>= 1) {
        if (hh < s) red[hh] += red[hh + s];
        __syncthreads();
    }
    if (hh == 0) aOut[row] = red[0];
}

// ---------------- per-layer: masked softmax -> w ----------------------------
// Middle-layer mask (NOTE the broadcast in the reference applies to COLUMN j):
//   mask[i,j] = (j > i && j <= len) || (j == len)
__global__ void softmax_kernel(const float* __restrict__ S2, const float* __restrict__ aArr,
                               const float* __restrict__ b_d1, const float* __restrict__ p,
                               const int* __restrict__ clen, int layer,
                               float* __restrict__ w) {
    int bi = blockIdx.x, b = bi / NN, i = bi % NN;
    int j = threadIdx.x;  // 128 threads
    int len = clen[b] / TT;
    bool m = false;
    if (j < NN) {
        if (layer == 0)             m = (j == 1);
        else if (layer == NLAY - 1) m = (j == len);
        else                        m = ((j > i) && (j <= len)) || (j == len);
    }
    float logit = m ? (aArr[bi] + S2[(size_t)bi * NN + j] + b_d1[0]) : -1e30f;
    __shared__ float red[128];
    red[threadIdx.x] = logit; __syncthreads();
    for (int s = 64; s > 0; s >>= 1) {
        if (threadIdx.x < s) red[threadIdx.x] = fmaxf(red[threadIdx.x], red[threadIdx.x + s]);
        __syncthreads();
    }
    float mx = red[0]; __syncthreads();
    float e = m ? __expf(logit - mx) : 0.f;
    red[threadIdx.x] = e; __syncthreads();
    for (int s = 64; s > 0; s >>= 1) {
        if (threadIdx.x < s) red[threadIdx.x] += red[threadIdx.x + s];
        __syncthreads();
    }
    float sum = red[0];
    if (j < NN) w[(size_t)bi * NN + j] = p[bi] * (e / sum);
}

// ---------------- per-layer: gated aggregation ------------------------------
__global__ void agg_kernel(const float* __restrict__ w, const float* __restrict__ pm4,
                           const float* __restrict__ hWhb,
                           const float* __restrict__ cIn, const float* __restrict__ hIn,
                           float* __restrict__ cOut, float* __restrict__ hOut,
                           float* __restrict__ pOut) {
    int bj = blockIdx.x, b = bj / NN, j = bj % NN;
    int hh = threadIdx.x;  // 256
    __shared__ float sw[NN];
    if (hh < NN) sw[hh] = w[((size_t)(b * NN + hh)) * NN + j];
    __syncthreads();
    const float* pj = pm4 + (size_t)bj * H4;
    float zj0 = pj[hh], zj1 = pj[HD + hh], zj2 = pj[2 * HD + hh], zj3 = pj[3 * HD + hh];
    float accC = 0.f, accH = 0.f, wsum = 0.f;
    for (int i = 0; i < NN; i++) {
        float wi = sw[i];
        wsum += wi;
        if (wi == 0.f) continue;
        int ri = b * NN + i;
        float cp, hp;
        if (j > i) {
            const float* pi = pm4 + (size_t)ri * H4;
            const float* hw = hWhb + (size_t)ri * H4;
            float zi = zj0 - pi[hh]          + hw[hh];
            float zf = zj1 - pi[HD + hh]     + hw[HD + hh];
            float zg = zj2 - pi[2 * HD + hh] + hw[2 * HD + hh];
            float zo = zj3 - pi[3 * HD + hh] + hw[3 * HD + hh];
            float cold = cIn[(size_t)ri * HD + hh];
            cp = sigf(zf) * cold + sigf(zi) * tanhr(zg);
            hp = sigf(zo) * tanhr(cp);
        } else {
            cp = cIn[(size_t)ri * HD + hh];
            hp = hIn[(size_t)ri * HD + hh];
        }
        accC += wi * cp;
        accH += wi * hp;
    }
    float denom = wsum + 1e-7f;
    cOut[(size_t)bj * HD + hh] = accC / denom;
    hOut[(size_t)bj * HD + hh] = accH / denom;
    if (hh == 0) pOut[bj] = wsum;
}

// ---------------------------------------------------------------------------
static float* sym(const void* s) {
    void* p = nullptr;
    cudaGetSymbolAddress(&p, s);
    return (float*)p;
}

extern "C" void kernel_launch(void* const* d_in, const int* in_sizes, int n_in,
                              void* d_out, int out_size) {
    const int*   ids    = (const int*)d_in[0];
    const int*   clen   = (const int*)d_in[1];
    const float* embed  = (const float*)d_in[2];
    const float* Wx_s   = (const float*)d_in[3];
    const float* Wh_s   = (const float*)d_in[4];
    const float* b_s    = (const float*)d_in[5];
    const float* W_se   = (const float*)d_in[6];
    const float* b_se   = (const float*)d_in[7];
    const float* Wx_e   = (const float*)d_in[8];
    const float* Wh_e   = (const float*)d_in[9];
    const float* b_e    = (const float*)d_in[10];
    const float* W_hk   = (const float*)d_in[11];
    const float* b_hk   = (const float*)d_in[12];
    const float* W_sd   = (const float*)d_in[13];
    const float* b_sd   = (const float*)d_in[14];
    const float* W_d1   = (const float*)d_in[15];
    const float* b_d1   = (const float*)d_in[16];
    const float* init_a = (const float*)d_in[17];
    const float* init_b = (const float*)d_in[18];

    float* xw   = sym(g_xw);
    float* zbuf = sym(g_z);
    float* c0   = sym(g_c0);
    float* h0   = sym(g_h0);
    float* pref = sym(g_pref);
    float* Me   = sym(g_Me);
    float* Ms   = sym(g_Ms);
    float* be   = sym(g_be);
    float* bs   = sym(g_bs);
    float* pm4  = sym(g_pm4);
    float* prS  = sym(g_prefS);
    float* S2   = sym(g_S2);
    float* aA   = sym(g_aArr);
    float* hWhb = sym(g_hWhb);
    float* wM   = sym(g_w);
    float* cA   = sym(g_cA);
    float* hA   = sym(g_hA);
    float* cB   = sym(g_cB);
    float* hB   = sym(g_hB);
    float* pA   = sym(g_pA);
    float* pB   = sym(g_pB);

    // 1) token projection: xw = embed[ids] @ Wx_s + b_s   [3072,1024]
    gemm_kernel<<<dim3(TOK / BM, H4 / BN), 256>>>(embed, ids, Wx_s, b_s, nullptr, 0,
                                                  xw, TOK, HD, H4);
    // 2) statement LSTM, step 0 (h=c=0 so z = xw[t=0])
    lstm_gate_kernel<<<SEQS, 256>>>(xw, TT * H4, c0, h0, 1);
    // steps 1..7: z = h @ Wh_s + xw[:,t]
    for (int t = 1; t < TT; t++) {
        gemm_kernel<<<dim3(SEQS / BM, H4 / BN), 256>>>(h0, nullptr, Wh_s, nullptr,
                                                       xw + (size_t)t * H4, TT * H4,
                                                       zbuf, SEQS, HD, H4);
        lstm_gate_kernel<<<SEQS, 256>>>(zbuf, H4, c0, h0, 0);
    }
    // 3) prefix sums over statement embeddings
    cumsum_kernel<<<BB, HD>>>(h0, pref);
    // 4) composed weights/biases
    gemm_kernel<<<dim3(HD / BM, H4 / BN), 256>>>(W_se, nullptr, Wx_e, nullptr, nullptr, 0,
                                                 Me, HD, HD, H4);
    gemm_kernel<<<dim3(HD / BM, HD / BN), 256>>>(W_se, nullptr, W_sd, nullptr, nullptr, 0,
                                                 Ms, HD, HD, HD);
    vecmat_kernel<<<(H4 + 255) / 256, 256>>>(b_se, Wx_e, b_e, be, HD, H4);
    vecmat_kernel<<<1, 256>>>(b_se, W_sd, b_sd, bs, HD, HD);
    // 5) projected prefix tables
    gemm_kernel<<<dim3((ROWS + BM - 1) / BM, H4 / BN), 256>>>(pref, nullptr, Me, nullptr,
                                                              nullptr, 0, pm4, ROWS, HD, H4);
    gemm_kernel<<<dim3((ROWS + BM - 1) / BM, HD / BN), 256>>>(pref, nullptr, Ms, nullptr,
                                                              nullptr, 0, prS, ROWS, HD, HD);
    // 6) layer-invariant logit term
    s2_kernel<<<ROWS, 128>>>(prS, bs, W_d1, S2);
    // 7) execution state init
    init_exec_kernel<<<ROWS, 256>>>(init_a, init_b, cA, hA, pA);

    // 8) execution layers
    float *cS = cA, *hS = hA, *pS = pA, *cD = cB, *hD = hB, *pD = pB;
    for (int layer = 0; layer < NLAY; layer++) {
        hkey_kernel<<<ROWS, 256>>>(hS, W_hk, b_hk, W_d1, aA);
        gemm_kernel<<<dim3((ROWS + BM - 1) / BM, H4 / BN), 256>>>(hS, nullptr, Wh_e, be,
                                                                  nullptr, 0, hWhb,
                                                                  ROWS, HD, H4);
        softmax_kernel<<<ROWS, 128>>>(S2, aA, b_d1, pS, clen, layer, wM);
        float* hOutPtr = (layer == NLAY - 1) ? (float*)d_out : hD;
        agg_kernel<<<ROWS, 256>>>(wM, pm4, hWhb, cS, hS, cD, hOutPtr, pD);
        float* t;
        t = cS; cS = cD; cD = t;
        t = hS; hS = hD; hD = t;
        t = pS; pS = pD; pD = t;
    }
}